// round 1
// baseline (speedup 1.0000x reference)
#include <cuda_runtime.h>
#include <cuda_bf16.h>

// ---------------- problem dims ----------------
#define B_    16
#define C0    8
#define T0_   32768
#define C1    64
#define T1_   16384
#define C2    128
#define T2_   8192
#define D_    64
#define T3_   4096
#define NC    512

// ---------------- scratch (device globals; no allocation) ----------------
__device__ float g_z1[B_ * C1 * T1_];   // 64 MB
__device__ float g_z2[B_ * C2 * T2_];   // 64 MB
__device__ float g_ze[B_ * D_ * T3_];   // 16 MB
__device__ float g_zq[B_ * D_ * T3_];   // 16 MB
__device__ float g_r1[B_ * C2 * T2_];   // 64 MB
__device__ float g_r2[B_ * C1 * T1_];   // 64 MB
__device__ int    g_hist[B_ * NC];
__device__ double g_vq_sse;
__device__ double g_rec_sse;

// ---------------- init ----------------
__global__ void k_init() {
    int i = blockIdx.x * blockDim.x + threadIdx.x;
    if (i < B_ * NC) g_hist[i] = 0;
    if (i == 0) { g_vq_sse = 0.0; g_rec_sse = 0.0; }
}

// ---------------- conv1: x[16,8,32768] -> z1[16,64,16384], k=7 s=2 p=3, relu ----
__global__ __launch_bounds__(256) void k_conv1(const float* __restrict__ x,
                                               const float* __restrict__ w1,
                                               const float* __restrict__ b1) {
    __shared__ float s[C0][264];
    int b = blockIdx.y, t0 = blockIdx.x * 128;
    int in0 = 2 * t0 - 3;
    for (int i = threadIdx.x; i < C0 * 262; i += 256) {
        int ic = i / 262, p = i - ic * 262;
        int g = in0 + p;
        s[ic][p] = (g >= 0 && g < T0_) ? x[(b * C0 + ic) * T0_ + g] : 0.f;
    }
    __syncthreads();
    int lane = threadIdx.x & 31, w = threadIdx.x >> 5;
    for (int ocb = 0; ocb < 8; ocb++) {
        int oc = w * 8 + ocb;                 // warp-uniform
        float bias = b1[oc];
        float a0 = bias, a1 = bias, a2 = bias, a3 = bias;
        const float* wp = w1 + oc * 56;
        #pragma unroll
        for (int ic = 0; ic < C0; ic++) {
            #pragma unroll
            for (int k = 0; k < 7; k++) {
                float wv = wp[ic * 7 + k];
                a0 += s[ic][2 * lane + k]       * wv;
                a1 += s[ic][2 * lane + 64 + k]  * wv;
                a2 += s[ic][2 * lane + 128 + k] * wv;
                a3 += s[ic][2 * lane + 192 + k] * wv;
            }
        }
        float* o = g_z1 + (b * C1 + oc) * T1_ + t0 + lane;
        o[0]  = fmaxf(a0, 0.f); o[32] = fmaxf(a1, 0.f);
        o[64] = fmaxf(a2, 0.f); o[96] = fmaxf(a3, 0.f);
    }
}

// ---------------- conv2: z1 -> z2[16,128,8192], k=5 s=2 p=2, relu ----------
__global__ __launch_bounds__(256) void k_conv2(const float* __restrict__ w2,
                                               const float* __restrict__ b2) {
    __shared__ float s[C1][132];
    int b = blockIdx.y, t0 = blockIdx.x * 64;
    int in0 = 2 * t0 - 2;
    const float* xin = g_z1 + b * C1 * T1_;
    for (int i = threadIdx.x; i < C1 * 131; i += 256) {
        int ic = i / 131, p = i - ic * 131;
        int g = in0 + p;
        s[ic][p] = (g >= 0 && g < T1_) ? xin[ic * T1_ + g] : 0.f;
    }
    __syncthreads();
    int lane = threadIdx.x & 31, w = threadIdx.x >> 5;
    for (int ocb = 0; ocb < 16; ocb++) {
        int oc = w * 16 + ocb;                // warp-uniform
        float bias = b2[oc];
        float a0 = bias, a1 = bias;
        const float* wp = w2 + oc * 320;
        for (int ic = 0; ic < C1; ic++) {
            const float2* sp0 = (const float2*)&s[ic][2 * lane];
            const float2* sp1 = (const float2*)&s[ic][2 * lane + 64];
            float2 x0 = sp0[0], x1 = sp0[1], x2 = sp0[2];
            float2 y0 = sp1[0], y1 = sp1[1], y2 = sp1[2];
            float wv0 = wp[ic * 5 + 0], wv1 = wp[ic * 5 + 1], wv2 = wp[ic * 5 + 2];
            float wv3 = wp[ic * 5 + 3], wv4 = wp[ic * 5 + 4];
            a0 += x0.x * wv0 + x0.y * wv1 + x1.x * wv2 + x1.y * wv3 + x2.x * wv4;
            a1 += y0.x * wv0 + y0.y * wv1 + y1.x * wv2 + y1.y * wv3 + y2.x * wv4;
        }
        float* o = g_z2 + (b * C2 + oc) * T2_ + t0 + lane;
        o[0]  = fmaxf(a0, 0.f);
        o[32] = fmaxf(a1, 0.f);
    }
}

// ---------------- conv3: z2 -> z_e[16,64,4096], k=3 s=2 p=1 ----------------
__global__ __launch_bounds__(256) void k_conv3(const float* __restrict__ w3,
                                               const float* __restrict__ b3) {
    __shared__ float s[C2][68];
    int b = blockIdx.y, t0 = blockIdx.x * 32;
    int in0 = 2 * t0 - 1;
    const float* xin = g_z2 + b * C2 * T2_;
    for (int i = threadIdx.x; i < C2 * 65; i += 256) {
        int ic = i / 65, p = i - ic * 65;
        int g = in0 + p;
        s[ic][p] = (g >= 0 && g < T2_) ? xin[ic * T2_ + g] : 0.f;
    }
    __syncthreads();
    int lane = threadIdx.x & 31, w = threadIdx.x >> 5;
    for (int ocb = 0; ocb < 8; ocb++) {
        int oc = w * 8 + ocb;
        float acc = b3[oc];
        const float* wp = w3 + oc * 384;
        for (int ic = 0; ic < C2; ic++) {
            float2 x0 = *(const float2*)&s[ic][2 * lane];
            float  x2 = s[ic][2 * lane + 2];
            acc += x0.x * wp[ic * 3 + 0] + x0.y * wp[ic * 3 + 1] + x2 * wp[ic * 3 + 2];
        }
        g_ze[(b * D_ + oc) * T3_ + t0 + lane] = acc;
    }
}

// ---------------- quantize: z_e + codebook -> z_q, hist, vq SSE -------------
__global__ __launch_bounds__(256) void k_quant(const float* __restrict__ cb) {
    __shared__ float scb[128 * 64];
    __shared__ float snorm[128];
    __shared__ int   shist[NC];
    __shared__ float sred[8];
    int tid = threadIdx.x;
    int g = blockIdx.x * 256 + tid;
    int b = g >> 12, t = g & 4095;

    for (int i = tid; i < NC; i += 256) shist[i] = 0;

    float z[64];
    const float* zp = g_ze + b * D_ * T3_ + t;
    #pragma unroll
    for (int d = 0; d < 64; d++) z[d] = zp[d * T3_];
    float zz = 0.f;
    #pragma unroll
    for (int d = 0; d < 64; d++) zz += z[d] * z[d];

    float best = 3.4e38f;
    int bi = 0;
    for (int ch = 0; ch < 4; ch++) {
        __syncthreads();
        for (int i = tid; i < 128 * 64; i += 256) scb[i] = cb[ch * 8192 + i];
        __syncthreads();
        for (int c = tid; c < 128; c += 256) {
            float n = 0.f;
            for (int d = 0; d < 64; d++) { float v = scb[c * 64 + d]; n += v * v; }
            snorm[c] = n;
        }
        __syncthreads();
        for (int c = 0; c < 128; c++) {
            const float4* cbp = (const float4*)(scb + c * 64);
            float dot = 0.f;
            #pragma unroll
            for (int q = 0; q < 16; q++) {
                float4 v = cbp[q];
                dot += z[4 * q] * v.x + z[4 * q + 1] * v.y + z[4 * q + 2] * v.z + z[4 * q + 3] * v.w;
            }
            float d2 = zz - 2.f * dot + snorm[c];
            if (d2 < best) { best = d2; bi = ch * 128 + c; }
        }
    }

    // exact SSE against chosen code + write z_q
    const float* cbest = cb + bi * 64;
    float* zqp = g_zq + b * D_ * T3_ + t;
    float sse = 0.f;
    #pragma unroll
    for (int d = 0; d < 64; d++) {
        float cv = __ldg(&cbest[d]);
        float df = z[d] - cv;
        sse += df * df;
        zqp[d * T3_] = cv;
    }
    atomicAdd(&shist[bi], 1);

    // block reduce sse
    int lane = tid & 31, w = tid >> 5;
    #pragma unroll
    for (int off = 16; off; off >>= 1) sse += __shfl_down_sync(0xffffffffu, sse, off);
    if (lane == 0) sred[w] = sse;
    __syncthreads();
    if (tid < 8) {
        float v = sred[tid];
        #pragma unroll
        for (int off = 4; off; off >>= 1) v += __shfl_down_sync(0xffu, v, off);
        if (tid == 0) atomicAdd(&g_vq_sse, (double)v);
    }
    __syncthreads();
    for (int i = tid; i < NC; i += 256)
        if (shist[i]) atomicAdd(&g_hist[b * NC + i], shist[i]);
}

// ---------------- conditioning = hist @ codebook / T3 ----------------------
__global__ void k_cond(const float* __restrict__ cb, float* __restrict__ out) {
    int b = blockIdx.x, d = threadIdx.x;
    float sum = 0.f;
    for (int c = 0; c < NC; c++)
        sum += (float)g_hist[b * NC + c] * cb[c * 64 + d];
    out[b * 64 + d] = sum * (1.f / (float)T3_);
}

// ---------------- decT1: z_q[16,64,4096] -> r1[16,128,8192], k=4 s=2 p=1, relu
__global__ __launch_bounds__(256) void k_dec1(const float* __restrict__ dw1,
                                              const float* __restrict__ db1) {
    __shared__ float s[D_][66];
    int b = blockIdx.y, t0 = blockIdx.x * 128;
    int s0 = (t0 >> 1) - 1;
    const float* xin = g_zq + b * D_ * T3_;
    for (int i = threadIdx.x; i < D_ * 66; i += 256) {
        int ic = i / 66, p = i - ic * 66;
        int gg = s0 + p;
        s[ic][p] = (gg >= 0 && gg < T3_) ? xin[ic * T3_ + gg] : 0.f;
    }
    __syncthreads();
    int lane = threadIdx.x & 31, w = threadIdx.x >> 5;
    int par = lane & 1;
    int h = (lane >> 1) + 1;
    for (int ocb = 0; ocb < 16; ocb++) {
        int oc = w * 16 + ocb;
        float bias = db1[oc];
        float a0 = bias, a1 = bias, a2 = bias, a3 = bias;
        for (int ic = 0; ic < D_; ic++) {
            float4 wv = *(const float4*)&dw1[(ic * C2 + oc) * 4];
            float wa = par ? wv.x : wv.y;
            float wb = par ? wv.z : wv.w;
            int p0 = h + par;
            a0 += s[ic][p0]      * wa + s[ic][p0 - 1]  * wb;
            a1 += s[ic][p0 + 16] * wa + s[ic][p0 + 15] * wb;
            a2 += s[ic][p0 + 32] * wa + s[ic][p0 + 31] * wb;
            a3 += s[ic][p0 + 48] * wa + s[ic][p0 + 47] * wb;
        }
        float* o = g_r1 + (b * C2 + oc) * T2_ + t0 + lane;
        o[0]  = fmaxf(a0, 0.f); o[32] = fmaxf(a1, 0.f);
        o[64] = fmaxf(a2, 0.f); o[96] = fmaxf(a3, 0.f);
    }
}

// ---------------- decT2: r1 -> r2[16,64,16384], k=4 s=2 p=1, relu -----------
__global__ __launch_bounds__(256) void k_dec2(const float* __restrict__ dw2,
                                              const float* __restrict__ db2) {
    __shared__ float s[C2][66];
    int b = blockIdx.y, t0 = blockIdx.x * 128;
    int s0 = (t0 >> 1) - 1;
    const float* xin = g_r1 + b * C2 * T2_;
    for (int i = threadIdx.x; i < C2 * 66; i += 256) {
        int ic = i / 66, p = i - ic * 66;
        int gg = s0 + p;
        s[ic][p] = (gg >= 0 && gg < T2_) ? xin[ic * T2_ + gg] : 0.f;
    }
    __syncthreads();
    int lane = threadIdx.x & 31, w = threadIdx.x >> 5;
    int par = lane & 1;
    int h = (lane >> 1) + 1;
    for (int ocb = 0; ocb < 8; ocb++) {
        int oc = w * 8 + ocb;
        float bias = db2[oc];
        float a0 = bias, a1 = bias, a2 = bias, a3 = bias;
        for (int ic = 0; ic < C2; ic++) {
            float4 wv = *(const float4*)&dw2[(ic * C1 + oc) * 4];
            float wa = par ? wv.x : wv.y;
            float wb = par ? wv.z : wv.w;
            int p0 = h + par;
            a0 += s[ic][p0]      * wa + s[ic][p0 - 1]  * wb;
            a1 += s[ic][p0 + 16] * wa + s[ic][p0 + 15] * wb;
            a2 += s[ic][p0 + 32] * wa + s[ic][p0 + 31] * wb;
            a3 += s[ic][p0 + 48] * wa + s[ic][p0 + 47] * wb;
        }
        float* o = g_r2 + (b * C1 + oc) * T1_ + t0 + lane;
        o[0]  = fmaxf(a0, 0.f); o[32] = fmaxf(a1, 0.f);
        o[64] = fmaxf(a2, 0.f); o[96] = fmaxf(a3, 0.f);
    }
}

// ---------------- decT3 fused with recon-MSE: r2 -> (x_recon - x)^2 sum -----
__global__ __launch_bounds__(256) void k_dec3(const float* __restrict__ dw3,
                                              const float* __restrict__ db3,
                                              const float* __restrict__ x) {
    __shared__ float s[C1][132];
    __shared__ float sred[8];
    int b = blockIdx.y, t0 = blockIdx.x * 256;
    int s0 = (t0 >> 1) - 1;
    const float* xin = g_r2 + b * C1 * T1_;
    for (int i = threadIdx.x; i < C1 * 130; i += 256) {
        int ic = i / 130, p = i - ic * 130;
        int gg = s0 + p;
        s[ic][p] = (gg >= 0 && gg < T1_) ? xin[ic * T1_ + gg] : 0.f;
    }
    __syncthreads();
    int lane = threadIdx.x & 31, w = threadIdx.x >> 5;
    int par = lane & 1;
    int h = (lane >> 1) + 1;
    int oc = w;  // 8 warps <-> 8 output channels
    float a[8];
    float bias = db3[oc];
    #pragma unroll
    for (int tt = 0; tt < 8; tt++) a[tt] = bias;
    for (int ic = 0; ic < C1; ic++) {
        float4 wv = *(const float4*)&dw3[(ic * C0 + oc) * 4];
        float wa = par ? wv.x : wv.y;
        float wb = par ? wv.z : wv.w;
        int p0 = h + par;
        #pragma unroll
        for (int tt = 0; tt < 8; tt++)
            a[tt] += s[ic][p0 + 16 * tt] * wa + s[ic][p0 + 16 * tt - 1] * wb;
    }
    const float* xr = x + (b * C0 + oc) * T0_ + t0 + lane;
    float ssq = 0.f;
    #pragma unroll
    for (int tt = 0; tt < 8; tt++) {
        float d = a[tt] - xr[32 * tt];
        ssq += d * d;
    }
    #pragma unroll
    for (int off = 16; off; off >>= 1) ssq += __shfl_down_sync(0xffffffffu, ssq, off);
    if (lane == 0) sred[w] = ssq;
    __syncthreads();
    if (threadIdx.x < 8) {
        float v = sred[threadIdx.x];
        #pragma unroll
        for (int off = 4; off; off >>= 1) v += __shfl_down_sync(0xffu, v, off);
        if (threadIdx.x == 0) atomicAdd(&g_rec_sse, (double)v);
    }
}

// ---------------- finalize scalars -----------------------------------------
__global__ void k_fin(float* __restrict__ out, int out_size) {
    if (out_size >= 1027) {
        float vq = (float)(g_vq_sse / (double)(B_ * D_ * T3_));
        out[1024] = vq;
        out[1025] = vq;
        out[1026] = (float)(g_rec_sse / (double)(B_ * C0 * T0_));
    }
}

// ---------------- launch ----------------------------------------------------
extern "C" void kernel_launch(void* const* d_in, const int* in_sizes, int n_in,
                              void* d_out, int out_size) {
    const float* x   = (const float*)d_in[0];
    const float* w1  = (const float*)d_in[1];
    const float* b1  = (const float*)d_in[2];
    const float* w2  = (const float*)d_in[3];
    const float* b2  = (const float*)d_in[4];
    const float* w3  = (const float*)d_in[5];
    const float* b3  = (const float*)d_in[6];
    const float* cb  = (const float*)d_in[7];
    const float* dw1 = (const float*)d_in[8];
    const float* db1 = (const float*)d_in[9];
    const float* dw2 = (const float*)d_in[10];
    const float* db2 = (const float*)d_in[11];
    const float* dw3 = (const float*)d_in[12];
    const float* db3 = (const float*)d_in[13];
    float* out = (float*)d_out;

    k_init<<<32, 256>>>();
    k_conv1<<<dim3(T1_ / 128, B_), 256>>>(x, w1, b1);
    k_conv2<<<dim3(T2_ / 64,  B_), 256>>>(w2, b2);
    k_conv3<<<dim3(T3_ / 32,  B_), 256>>>(w3, b3);
    k_quant<<<(B_ * T3_) / 256, 256>>>(cb);
    k_cond<<<B_, 64>>>(cb, out);
    k_dec1<<<dim3(T2_ / 128, B_), 256>>>(dw1, db1);
    k_dec2<<<dim3(T1_ / 128, B_), 256>>>(dw2, db2);
    k_dec3<<<dim3(T0_ / 256, B_), 256>>>(dw3, db3, x);
    k_fin<<<1, 1>>>(out, out_size);
}

// round 2
// speedup vs baseline: 2.3372x; 2.3372x over previous
#include <cuda_runtime.h>
#include <cuda_bf16.h>

// ---------------- problem dims ----------------
#define B_    16
#define C0    8
#define T0_   32768
#define C1    64
#define T1_   16384
#define C2    128
#define T2_   8192
#define D_    64
#define T3_   4096
#define NC    512

typedef unsigned long long ull;

// ---------------- f32x2 helpers ----------------
__device__ __forceinline__ ull pk(float lo, float hi) {
    ull r; asm("mov.b64 %0, {%1, %2};" : "=l"(r) : "f"(lo), "f"(hi)); return r;
}
__device__ __forceinline__ void upk(ull v, float& lo, float& hi) {
    asm("mov.b64 {%0, %1}, %2;" : "=f"(lo), "=f"(hi) : "l"(v));
}
__device__ __forceinline__ ull ffma2(ull a, ull b, ull c) {
    ull d; asm("fma.rn.f32x2 %0, %1, %2, %3;" : "=l"(d) : "l"(a), "l"(b), "l"(c)); return d;
}

// ---------------- scratch (device globals; no allocation) ----------------
__device__ float g_z1[B_ * C1 * T1_];
__device__ float g_z2[B_ * C2 * T2_];
__device__ float g_ze[B_ * D_ * T3_];
__device__ float g_zq[B_ * D_ * T3_];
__device__ float g_r1[B_ * C2 * T2_];
__device__ float g_r2[B_ * C1 * T1_];
__device__ int    g_hist[B_ * NC];
__device__ double g_vq_sse;
__device__ double g_rec_sse;

// ---------------- init ----------------
__global__ void k_init() {
    int i = blockIdx.x * blockDim.x + threadIdx.x;
    if (i < B_ * NC) g_hist[i] = 0;
    if (i == 0) { g_vq_sse = 0.0; g_rec_sse = 0.0; }
}

// ============================================================================
// conv1: x[16,8,32768] -> z1[16,64,16384], k=7 s=2 p=3, relu
// phases: out[t] = xe[t-1..t+1]*w{1,3,5} + xo[t-2..t+1]*w{0,2,4,6}
// tile: 256 outputs/block, thread TT=8, warp TO=8 ocs in 2 quads of 4
// ============================================================================
__global__ __launch_bounds__(256) void k_conv1(const float* __restrict__ x,
                                               const float* __restrict__ w1,
                                               const float* __restrict__ b1) {
    __shared__ float se[C0][260];   // se[ic][j] = X[2t0-2+2j], j<258
    __shared__ float so[C0][264];   // so[ic][j] = X[2t0-3+2j], j<259
    int b = blockIdx.y, t0 = blockIdx.x * 256;
    const float* xr = x + b * C0 * T0_;
    for (int idx = threadIdx.x; idx < C0 * 259; idx += 256) {
        int ic = idx / 259, j = idx - ic * 259;
        int f = 2 * t0 - 4 + 2 * j;
        float a  = (f >= 0 && f < T0_)         ? xr[ic * T0_ + f]     : 0.f;
        float bb = (f + 1 >= 0 && f + 1 < T0_) ? xr[ic * T0_ + f + 1] : 0.f;
        if (j >= 1) se[ic][j - 1] = a;
        so[ic][j] = bb;
    }
    __syncthreads();
    int lane = threadIdx.x & 31, w = threadIdx.x >> 5;
    int L = lane * 8;
    for (int q = 0; q < 2; q++) {
        int oc = w * 8 + q * 4;
        float acc[4][8];
        #pragma unroll
        for (int i = 0; i < 4; i++) {
            float bv = b1[oc + i];
            #pragma unroll
            for (int u = 0; u < 8; u++) acc[i][u] = bv;
        }
        #pragma unroll
        for (int ic = 0; ic < C0; ic++) {
            const float* seb = &se[ic][L];
            const float* sob = &so[ic][L];
            float4 ea = *(const float4*)(seb);
            float4 eb = *(const float4*)(seb + 4);
            float2 ec = *(const float2*)(seb + 8);
            float4 oa = *(const float4*)(sob);
            float4 ob = *(const float4*)(sob + 4);
            float2 ocv = *(const float2*)(sob + 8);
            float od = sob[10];
            float e[10] = {ea.x, ea.y, ea.z, ea.w, eb.x, eb.y, eb.z, eb.w, ec.x, ec.y};
            float o[11] = {oa.x, oa.y, oa.z, oa.w, ob.x, ob.y, ob.z, ob.w, ocv.x, ocv.y, od};
            #pragma unroll
            for (int i = 0; i < 4; i++) {
                const float* wp = w1 + (oc + i) * 56 + ic * 7;
                float w0 = wp[0], w1_ = wp[1], w2 = wp[2], w3 = wp[3];
                float w4 = wp[4], w5 = wp[5], w6 = wp[6];
                #pragma unroll
                for (int u = 0; u < 8; u++) {
                    float s = acc[i][u];
                    s += e[u] * w1_ + e[u + 1] * w3 + e[u + 2] * w5;
                    s += o[u] * w0 + o[u + 1] * w2 + o[u + 2] * w4 + o[u + 3] * w6;
                    acc[i][u] = s;
                }
            }
        }
        #pragma unroll
        for (int i = 0; i < 4; i++) {
            float* op = g_z1 + (b * C1 + oc + i) * T1_ + t0 + L;
            float4 s0 = {fmaxf(acc[i][0], 0.f), fmaxf(acc[i][1], 0.f),
                         fmaxf(acc[i][2], 0.f), fmaxf(acc[i][3], 0.f)};
            float4 s1 = {fmaxf(acc[i][4], 0.f), fmaxf(acc[i][5], 0.f),
                         fmaxf(acc[i][6], 0.f), fmaxf(acc[i][7], 0.f)};
            *(float4*)op = s0;
            *(float4*)(op + 4) = s1;
        }
    }
}

// ============================================================================
// conv2: z1 -> z2[16,128,8192], k=5 s=2 p=2, relu
// out[t] = xe[t-1]w0 + xo[t-1]w1 + xe[t]w2 + xo[t]w3 + xe[t+1]w4
// tile 128 outputs, grid.z=2 splits ocs; thread TT=4, 2 quads of TO=4, 2 ic chunks
// ============================================================================
__global__ __launch_bounds__(256) void k_conv2(const float* __restrict__ w2,
                                               const float* __restrict__ b2) {
    __shared__ float se[32][132];   // se[ic][j] = X[2t0-2+2j], j<130
    __shared__ float so[32][132];   // so[ic][j] = X[2t0-1+2j], j<129
    int b = blockIdx.y, t0 = blockIdx.x * 128, zz = blockIdx.z;
    const float* xin = g_z1 + b * C1 * T1_;
    int lane = threadIdx.x & 31, w = threadIdx.x >> 5;
    int L = lane * 4;
    float acc[2][4][4];
    #pragma unroll
    for (int q = 0; q < 2; q++) {
        int oc = zz * 64 + w * 8 + q * 4;
        #pragma unroll
        for (int i = 0; i < 4; i++) {
            float bv = b2[oc + i];
            #pragma unroll
            for (int u = 0; u < 4; u++) acc[q][i][u] = bv;
        }
    }
    for (int ch = 0; ch < 2; ch++) {
        for (int idx = threadIdx.x; idx < 32 * 130; idx += 256) {
            int ic = idx / 130, j = idx - ic * 130;
            int icg = ch * 32 + ic;
            int f = 2 * t0 - 2 + 2 * j;
            float a  = (f >= 0 && f < T1_)         ? xin[icg * T1_ + f]     : 0.f;
            float bb = (f + 1 >= 0 && f + 1 < T1_) ? xin[icg * T1_ + f + 1] : 0.f;
            se[ic][j] = a;
            if (j < 129) so[ic][j] = bb;
        }
        __syncthreads();
        for (int ic = 0; ic < 32; ic++) {
            int icg = ch * 32 + ic;
            const float* seb = &se[ic][L];
            const float* sob = &so[ic][L];
            float4 ea = *(const float4*)(seb);
            float2 eb = *(const float2*)(seb + 4);
            float4 oa = *(const float4*)(sob);
            float ob = sob[4];
            float e[6] = {ea.x, ea.y, ea.z, ea.w, eb.x, eb.y};
            float o[5] = {oa.x, oa.y, oa.z, oa.w, ob};
            #pragma unroll
            for (int q = 0; q < 2; q++) {
                int oc = zz * 64 + w * 8 + q * 4;
                #pragma unroll
                for (int i = 0; i < 4; i++) {
                    const float* wp = w2 + (oc + i) * 320 + icg * 5;
                    float w0 = wp[0], w1_ = wp[1], w2_ = wp[2], w3 = wp[3], w4 = wp[4];
                    #pragma unroll
                    for (int u = 0; u < 4; u++) {
                        float s = acc[q][i][u];
                        s += e[u] * w0 + o[u] * w1_ + e[u + 1] * w2_;
                        s += o[u + 1] * w3 + e[u + 2] * w4;
                        acc[q][i][u] = s;
                    }
                }
            }
        }
        __syncthreads();
    }
    #pragma unroll
    for (int q = 0; q < 2; q++) {
        int oc = zz * 64 + w * 8 + q * 4;
        #pragma unroll
        for (int i = 0; i < 4; i++) {
            float* op = g_z2 + (b * C2 + oc + i) * T2_ + t0 + L;
            float4 s0 = {fmaxf(acc[q][i][0], 0.f), fmaxf(acc[q][i][1], 0.f),
                         fmaxf(acc[q][i][2], 0.f), fmaxf(acc[q][i][3], 0.f)};
            *(float4*)op = s0;
        }
    }
}

// ============================================================================
// conv3: z2 -> z_e[16,64,4096], k=3 s=2 p=1 (no relu)
// out[t] = xo[t-1]w0 + xe[t]w1 + xo[t]w2
// tile 128 outputs, thread TT=4, 2 quads of TO=4, 4 ic chunks of 32
// ============================================================================
__global__ __launch_bounds__(256) void k_conv3(const float* __restrict__ w3,
                                               const float* __restrict__ b3) {
    __shared__ float se[32][132];   // se[ic][j] = X[2t0+2j], j<128
    __shared__ float so[32][132];   // so[ic][j] = X[2t0-1+2j], j<129
    int b = blockIdx.y, t0 = blockIdx.x * 128;
    const float* xin = g_z2 + b * C2 * T2_;
    int lane = threadIdx.x & 31, w = threadIdx.x >> 5;
    int L = lane * 4;
    float acc[2][4][4];
    #pragma unroll
    for (int q = 0; q < 2; q++) {
        int oc = w * 8 + q * 4;
        #pragma unroll
        for (int i = 0; i < 4; i++) {
            float bv = b3[oc + i];
            #pragma unroll
            for (int u = 0; u < 4; u++) acc[q][i][u] = bv;
        }
    }
    for (int ch = 0; ch < 4; ch++) {
        for (int idx = threadIdx.x; idx < 32 * 129; idx += 256) {
            int ic = idx / 129, j = idx - ic * 129;
            int icg = ch * 32 + ic;
            int f = 2 * t0 - 2 + 2 * j;
            float a  = (f >= 0 && f < T2_)         ? xin[icg * T2_ + f]     : 0.f;
            float bb = (f + 1 >= 0 && f + 1 < T2_) ? xin[icg * T2_ + f + 1] : 0.f;
            if (j >= 1) se[ic][j - 1] = a;
            so[ic][j] = bb;
        }
        __syncthreads();
        for (int ic = 0; ic < 32; ic++) {
            int icg = ch * 32 + ic;
            float4 ea = *(const float4*)&se[ic][L];
            float4 oa = *(const float4*)&so[ic][L];
            float ob = so[ic][L + 4];
            float e[4] = {ea.x, ea.y, ea.z, ea.w};
            float o[5] = {oa.x, oa.y, oa.z, oa.w, ob};
            #pragma unroll
            for (int q = 0; q < 2; q++) {
                int oc = w * 8 + q * 4;
                #pragma unroll
                for (int i = 0; i < 4; i++) {
                    const float* wp = w3 + (oc + i) * 384 + icg * 3;
                    float w0 = wp[0], w1_ = wp[1], w2_ = wp[2];
                    #pragma unroll
                    for (int u = 0; u < 4; u++)
                        acc[q][i][u] += o[u] * w0 + e[u] * w1_ + o[u + 1] * w2_;
                }
            }
        }
        __syncthreads();
    }
    #pragma unroll
    for (int q = 0; q < 2; q++) {
        int oc = w * 8 + q * 4;
        #pragma unroll
        for (int i = 0; i < 4; i++) {
            float* op = g_ze + (b * D_ + oc + i) * T3_ + t0 + L;
            float4 s0 = {acc[q][i][0], acc[q][i][1], acc[q][i][2], acc[q][i][3]};
            *(float4*)op = s0;
        }
    }
}

// ============================================================================
// quantize: z_e + codebook -> z_q, hist, vq SSE (FFMA2 dot products)
// ============================================================================
__global__ __launch_bounds__(256) void k_quant(const float* __restrict__ cb) {
    __shared__ __align__(16) float scb[128 * 64];
    __shared__ float snorm[128];
    __shared__ int   shist[NC];
    __shared__ float sred[8];
    int tid = threadIdx.x;
    int g = blockIdx.x * 256 + tid;
    int b = g >> 12, t = g & 4095;

    for (int i = tid; i < NC; i += 256) shist[i] = 0;

    float z[64];
    const float* zp = g_ze + b * D_ * T3_ + t;
    #pragma unroll
    for (int d = 0; d < 64; d++) z[d] = zp[d * T3_];
    float zz = 0.f;
    #pragma unroll
    for (int d = 0; d < 64; d++) zz += z[d] * z[d];
    ull z2[32];
    #pragma unroll
    for (int q = 0; q < 32; q++) z2[q] = pk(z[2 * q], z[2 * q + 1]);

    float best = 3.4e38f;
    int bi = 0;
    for (int ch = 0; ch < 4; ch++) {
        __syncthreads();
        for (int i = tid; i < 128 * 64; i += 256) scb[i] = cb[ch * 8192 + i];
        __syncthreads();
        for (int c = tid; c < 128; c += 256) {
            float n = 0.f;
            for (int d = 0; d < 64; d++) { float v = scb[c * 64 + d]; n += v * v; }
            snorm[c] = n;
        }
        __syncthreads();
        for (int c = 0; c < 128; c++) {
            const ulonglong2* cp = (const ulonglong2*)(scb + c * 64);
            ull d0 = 0ull, d1 = 0ull;
            #pragma unroll
            for (int q = 0; q < 16; q++) {
                ulonglong2 pv = cp[q];
                d0 = ffma2(z2[2 * q],     pv.x, d0);
                d1 = ffma2(z2[2 * q + 1], pv.y, d1);
            }
            float a0, a1, a2, a3;
            upk(d0, a0, a1); upk(d1, a2, a3);
            float dot = (a0 + a1) + (a2 + a3);
            float d2 = zz - 2.f * dot + snorm[c];
            if (d2 < best) { best = d2; bi = ch * 128 + c; }
        }
    }

    // exact SSE against chosen code + write z_q
    const float* cbest = cb + bi * 64;
    float* zqp = g_zq + b * D_ * T3_ + t;
    float sse = 0.f;
    #pragma unroll
    for (int d = 0; d < 64; d++) {
        float cv = __ldg(&cbest[d]);
        float df = z[d] - cv;
        sse += df * df;
        zqp[d * T3_] = cv;
    }
    atomicAdd(&shist[bi], 1);

    int lane = tid & 31, w = tid >> 5;
    #pragma unroll
    for (int off = 16; off; off >>= 1) sse += __shfl_down_sync(0xffffffffu, sse, off);
    if (lane == 0) sred[w] = sse;
    __syncthreads();
    if (tid < 8) {
        float v = sred[tid];
        #pragma unroll
        for (int off = 4; off; off >>= 1) v += __shfl_down_sync(0xffu, v, off);
        if (tid == 0) atomicAdd(&g_vq_sse, (double)v);
    }
    __syncthreads();
    for (int i = tid; i < NC; i += 256)
        if (shist[i]) atomicAdd(&g_hist[b * NC + i], shist[i]);
}

// ---------------- conditioning = hist @ codebook / T3 ----------------------
__global__ void k_cond(const float* __restrict__ cb, float* __restrict__ out) {
    int b = blockIdx.x, d = threadIdx.x;
    float sum = 0.f;
    for (int c = 0; c < NC; c++)
        sum += (float)g_hist[b * NC + c] * cb[c * 64 + d];
    out[b * 64 + d] = sum * (1.f / (float)T3_);
}

// ============================================================================
// decoder convT pattern: out[2m] = x[m-1]w3 + x[m]w1 ; out[2m+1] = x[m]w2 + x[m+1]w0
// packed: acc2(2m,2m+1) += {x[m-1],x[m]}*{w3,w2} + {x[m],x[m+1]}*{w1,w0}
// ============================================================================

// decT1: z_q[16,64,4096] -> r1[16,128,8192], relu. tile: 128 inputs -> 256 outputs
__global__ __launch_bounds__(256) void k_dec1(const float* __restrict__ dw1,
                                              const float* __restrict__ db1) {
    __shared__ float s[64][132];    // s[ic][j] = X[m0-1+j], j<130
    int b = blockIdx.y, m0 = blockIdx.x * 128;
    const float* xin = g_zq + b * D_ * T3_;
    for (int idx = threadIdx.x; idx < 64 * 130; idx += 256) {
        int ic = idx / 130, j = idx - ic * 130;
        int gg = m0 - 1 + j;
        s[ic][j] = (gg >= 0 && gg < T3_) ? xin[ic * T3_ + gg] : 0.f;
    }
    __syncthreads();
    int lane = threadIdx.x & 31, w = threadIdx.x >> 5;
    int M0 = lane * 4;
    for (int q = 0; q < 4; q++) {
        int oc = w * 16 + q * 4;
        ull acc[4][4];
        #pragma unroll
        for (int i = 0; i < 4; i++) {
            float bv = db1[oc + i];
            ull pb_ = pk(bv, bv);
            #pragma unroll
            for (int d = 0; d < 4; d++) acc[i][d] = pb_;
        }
        for (int ic = 0; ic < 64; ic++) {
            float4 v = *(const float4*)&s[ic][M0];
            float2 v2 = *(const float2*)&s[ic][M0 + 4];
            ull pm10 = pk(v.x, v.y), p01 = pk(v.y, v.z), p12 = pk(v.z, v.w);
            ull p23 = pk(v.w, v2.x), p34 = pk(v2.x, v2.y);
            #pragma unroll
            for (int i = 0; i < 4; i++) {
                float4 wv = *(const float4*)(dw1 + (ic * C2 + oc + i) * 4);
                ull w32 = pk(wv.w, wv.z), w10 = pk(wv.y, wv.x);
                acc[i][0] = ffma2(p01, w10, ffma2(pm10, w32, acc[i][0]));
                acc[i][1] = ffma2(p12, w10, ffma2(p01,  w32, acc[i][1]));
                acc[i][2] = ffma2(p23, w10, ffma2(p12,  w32, acc[i][2]));
                acc[i][3] = ffma2(p34, w10, ffma2(p23,  w32, acc[i][3]));
            }
        }
        #pragma unroll
        for (int i = 0; i < 4; i++) {
            float r0, r1, r2, r3, r4, r5, r6, r7;
            upk(acc[i][0], r0, r1); upk(acc[i][1], r2, r3);
            upk(acc[i][2], r4, r5); upk(acc[i][3], r6, r7);
            float* op = g_r1 + (b * C2 + oc + i) * T2_ + 2 * m0 + lane * 8;
            float4 s0 = {fmaxf(r0, 0.f), fmaxf(r1, 0.f), fmaxf(r2, 0.f), fmaxf(r3, 0.f)};
            float4 s1 = {fmaxf(r4, 0.f), fmaxf(r5, 0.f), fmaxf(r6, 0.f), fmaxf(r7, 0.f)};
            *(float4*)op = s0;
            *(float4*)(op + 4) = s1;
        }
    }
}

// decT2: r1[16,128,8192] -> r2[16,64,16384], relu. grid.z=2 splits ocs; 2 ic chunks
__global__ __launch_bounds__(256) void k_dec2(const float* __restrict__ dw2,
                                              const float* __restrict__ db2) {
    __shared__ float s[64][132];
    int b = blockIdx.y, m0 = blockIdx.x * 128, zz = blockIdx.z;
    const float* xin = g_r1 + b * C2 * T2_;
    int lane = threadIdx.x & 31, w = threadIdx.x >> 5;
    int M0 = lane * 4;
    int oc = zz * 32 + w * 4;
    ull acc[4][4];
    #pragma unroll
    for (int i = 0; i < 4; i++) {
        float bv = db2[oc + i];
        ull pb_ = pk(bv, bv);
        #pragma unroll
        for (int d = 0; d < 4; d++) acc[i][d] = pb_;
    }
    for (int ch = 0; ch < 2; ch++) {
        for (int idx = threadIdx.x; idx < 64 * 130; idx += 256) {
            int ic = idx / 130, j = idx - ic * 130;
            int icg = ch * 64 + ic;
            int gg = m0 - 1 + j;
            s[ic][j] = (gg >= 0 && gg < T2_) ? xin[icg * T2_ + gg] : 0.f;
        }
        __syncthreads();
        for (int ic = 0; ic < 64; ic++) {
            int icg = ch * 64 + ic;
            float4 v = *(const float4*)&s[ic][M0];
            float2 v2 = *(const float2*)&s[ic][M0 + 4];
            ull pm10 = pk(v.x, v.y), p01 = pk(v.y, v.z), p12 = pk(v.z, v.w);
            ull p23 = pk(v.w, v2.x), p34 = pk(v2.x, v2.y);
            #pragma unroll
            for (int i = 0; i < 4; i++) {
                float4 wv = *(const float4*)(dw2 + (icg * C1 + oc + i) * 4);
                ull w32 = pk(wv.w, wv.z), w10 = pk(wv.y, wv.x);
                acc[i][0] = ffma2(p01, w10, ffma2(pm10, w32, acc[i][0]));
                acc[i][1] = ffma2(p12, w10, ffma2(p01,  w32, acc[i][1]));
                acc[i][2] = ffma2(p23, w10, ffma2(p12,  w32, acc[i][2]));
                acc[i][3] = ffma2(p34, w10, ffma2(p23,  w32, acc[i][3]));
            }
        }
        __syncthreads();
    }
    #pragma unroll
    for (int i = 0; i < 4; i++) {
        float r0, r1, r2, r3, r4, r5, r6, r7;
        upk(acc[i][0], r0, r1); upk(acc[i][1], r2, r3);
        upk(acc[i][2], r4, r5); upk(acc[i][3], r6, r7);
        float* op = g_r2 + (b * C1 + oc + i) * T1_ + 2 * m0 + lane * 8;
        float4 s0 = {fmaxf(r0, 0.f), fmaxf(r1, 0.f), fmaxf(r2, 0.f), fmaxf(r3, 0.f)};
        float4 s1 = {fmaxf(r4, 0.f), fmaxf(r5, 0.f), fmaxf(r6, 0.f), fmaxf(r7, 0.f)};
        *(float4*)op = s0;
        *(float4*)(op + 4) = s1;
    }
}

// decT3 fused with recon-MSE: r2[16,64,16384] -> (x_recon - x)^2 sum (no relu)
__global__ __launch_bounds__(256) void k_dec3(const float* __restrict__ dw3,
                                              const float* __restrict__ db3,
                                              const float* __restrict__ x) {
    __shared__ float s[64][132];
    __shared__ float sred[8];
    int b = blockIdx.y, m0 = blockIdx.x * 128;
    const float* xin = g_r2 + b * C1 * T1_;
    for (int idx = threadIdx.x; idx < 64 * 130; idx += 256) {
        int ic = idx / 130, j = idx - ic * 130;
        int gg = m0 - 1 + j;
        s[ic][j] = (gg >= 0 && gg < T1_) ? xin[ic * T1_ + gg] : 0.f;
    }
    __syncthreads();
    int lane = threadIdx.x & 31, w = threadIdx.x >> 5;
    int M0 = lane * 4;
    int oc = w;                      // 8 warps <-> 8 output channels
    ull acc[4];
    {
        float bv = db3[oc];
        ull pb_ = pk(bv, bv);
        #pragma unroll
        for (int d = 0; d < 4; d++) acc[d] = pb_;
    }
    for (int ic = 0; ic < 64; ic++) {
        float4 v = *(const float4*)&s[ic][M0];
        float2 v2 = *(const float2*)&s[ic][M0 + 4];
        ull pm10 = pk(v.x, v.y), p01 = pk(v.y, v.z), p12 = pk(v.z, v.w);
        ull p23 = pk(v.w, v2.x), p34 = pk(v2.x, v2.y);
        float4 wv = *(const float4*)(dw3 + (ic * C0 + oc) * 4);
        ull w32 = pk(wv.w, wv.z), w10 = pk(wv.y, wv.x);
        acc[0] = ffma2(p01, w10, ffma2(pm10, w32, acc[0]));
        acc[1] = ffma2(p12, w10, ffma2(p01,  w32, acc[1]));
        acc[2] = ffma2(p23, w10, ffma2(p12,  w32, acc[2]));
        acc[3] = ffma2(p34, w10, ffma2(p23,  w32, acc[3]));
    }
    float r0, r1, r2, r3, r4, r5, r6, r7;
    upk(acc[0], r0, r1); upk(acc[1], r2, r3);
    upk(acc[2], r4, r5); upk(acc[3], r6, r7);
    const float* xr = x + (b * C0 + oc) * T0_ + 2 * m0 + lane * 8;
    float4 xa = *(const float4*)xr;
    float4 xb = *(const float4*)(xr + 4);
    float d0 = r0 - xa.x, d1 = r1 - xa.y, d2 = r2 - xa.z, d3 = r3 - xa.w;
    float d4 = r4 - xb.x, d5 = r5 - xb.y, d6 = r6 - xb.z, d7 = r7 - xb.w;
    float ssq = d0 * d0 + d1 * d1 + d2 * d2 + d3 * d3
              + d4 * d4 + d5 * d5 + d6 * d6 + d7 * d7;
    #pragma unroll
    for (int off = 16; off; off >>= 1) ssq += __shfl_down_sync(0xffffffffu, ssq, off);
    if (lane == 0) sred[w] = ssq;
    __syncthreads();
    if (threadIdx.x < 8) {
        float v = sred[threadIdx.x];
        #pragma unroll
        for (int off = 4; off; off >>= 1) v += __shfl_down_sync(0xffu, v, off);
        if (threadIdx.x == 0) atomicAdd(&g_rec_sse, (double)v);
    }
}

// ---------------- finalize scalars -----------------------------------------
__global__ void k_fin(float* __restrict__ out, int out_size) {
    if (out_size >= 1027) {
        float vq = (float)(g_vq_sse / (double)(B_ * D_ * T3_));
        out[1024] = vq;
        out[1025] = vq;
        out[1026] = (float)(g_rec_sse / (double)(B_ * C0 * T0_));
    }
}

// ---------------- launch ----------------------------------------------------
extern "C" void kernel_launch(void* const* d_in, const int* in_sizes, int n_in,
                              void* d_out, int out_size) {
    const float* x   = (const float*)d_in[0];
    const float* w1  = (const float*)d_in[1];
    const float* b1  = (const float*)d_in[2];
    const float* w2  = (const float*)d_in[3];
    const float* b2  = (const float*)d_in[4];
    const float* w3  = (const float*)d_in[5];
    const float* b3  = (const float*)d_in[6];
    const float* cb  = (const float*)d_in[7];
    const float* dw1 = (const float*)d_in[8];
    const float* db1 = (const float*)d_in[9];
    const float* dw2 = (const float*)d_in[10];
    const float* db2 = (const float*)d_in[11];
    const float* dw3 = (const float*)d_in[12];
    const float* db3 = (const float*)d_in[13];
    float* out = (float*)d_out;

    k_init<<<32, 256>>>();
    k_conv1<<<dim3(T1_ / 256, B_), 256>>>(x, w1, b1);
    k_conv2<<<dim3(T2_ / 128, B_, 2), 256>>>(w2, b2);
    k_conv3<<<dim3(T3_ / 128, B_), 256>>>(w3, b3);
    k_quant<<<(B_ * T3_) / 256, 256>>>(cb);
    k_cond<<<B_, 64>>>(cb, out);
    k_dec1<<<dim3(T3_ / 128, B_), 256>>>(dw1, db1);
    k_dec2<<<dim3(T2_ / 128, B_, 2), 256>>>(dw2, db2);
    k_dec3<<<dim3(T1_ / 128, B_), 256>>>(dw3, db3, x);
    k_fin<<<1, 1>>>(out, out_size);
}

// round 4
// speedup vs baseline: 2.3423x; 1.0022x over previous
#include <cuda_runtime.h>
#include <cuda_bf16.h>

// ---------------- problem dims ----------------
#define B_    16
#define C0    8
#define T0_   32768
#define C1    64
#define T1_   16384
#define C2    128
#define T2_   8192
#define D_    64
#define T3_   4096
#define NC    512

typedef unsigned long long ull;

// ---------------- f32x2 helpers ----------------
__device__ __forceinline__ ull pk(float lo, float hi) {
    ull r; asm("mov.b64 %0, {%1, %2};" : "=l"(r) : "f"(lo), "f"(hi)); return r;
}
__device__ __forceinline__ void upk(ull v, float& lo, float& hi) {
    asm("mov.b64 {%0, %1}, %2;" : "=f"(lo), "=f"(hi) : "l"(v));
}
__device__ __forceinline__ ull ffma2(ull a, ull b, ull c) {
    ull d; asm("fma.rn.f32x2 %0, %1, %2, %3;" : "=l"(d) : "l"(a), "l"(b), "l"(c)); return d;
}

// ---------------- scratch (device globals; no allocation) ----------------
__device__ float g_z1[B_ * C1 * T1_];
__device__ float g_z2[B_ * C2 * T2_];
__device__ float g_ze[B_ * D_ * T3_];
__device__ float g_zq[B_ * D_ * T3_];
__device__ float g_r1[B_ * C2 * T2_];
__device__ float g_r2[B_ * C1 * T1_];
__device__ int    g_hist[B_ * NC];
__device__ double g_vq_sse;
__device__ double g_rec_sse;

// ---------------- init ----------------
__global__ void k_init() {
    int i = blockIdx.x * blockDim.x + threadIdx.x;
    if (i < B_ * NC) g_hist[i] = 0;
    if (i == 0) { g_vq_sse = 0.0; g_rec_sse = 0.0; }
}

// ============================================================================
// conv1: x[16,8,32768] -> z1[16,64,16384], k=7 s=2 p=3, relu
// phases: out[t] = xe[t-1..t+1]*w{1,3,5} + xo[t-2..t+1]*w{0,2,4,6}
// tile: 256 outputs/block, thread TT=8, warp TO=8 ocs in 2 quads of 4
// ============================================================================
__global__ __launch_bounds__(256) void k_conv1(const float* __restrict__ x,
                                               const float* __restrict__ w1,
                                               const float* __restrict__ b1) {
    __shared__ float se[C0][260];   // se[ic][j] = X[2t0-2+2j], j<258
    __shared__ float so[C0][264];   // so[ic][j] = X[2t0-3+2j], j<259
    int b = blockIdx.y, t0 = blockIdx.x * 256;
    const float* xr = x + b * C0 * T0_;
    for (int idx = threadIdx.x; idx < C0 * 259; idx += 256) {
        int ic = idx / 259, j = idx - ic * 259;
        int f = 2 * t0 - 4 + 2 * j;
        float a  = (f >= 0 && f < T0_)         ? xr[ic * T0_ + f]     : 0.f;
        float bb = (f + 1 >= 0 && f + 1 < T0_) ? xr[ic * T0_ + f + 1] : 0.f;
        if (j >= 1) se[ic][j - 1] = a;
        so[ic][j] = bb;
    }
    __syncthreads();
    int lane = threadIdx.x & 31, w = threadIdx.x >> 5;
    int L = lane * 8;
    for (int q = 0; q < 2; q++) {
        int oc = w * 8 + q * 4;
        float acc[4][8];
        #pragma unroll
        for (int i = 0; i < 4; i++) {
            float bv = b1[oc + i];
            #pragma unroll
            for (int u = 0; u < 8; u++) acc[i][u] = bv;
        }
        #pragma unroll
        for (int ic = 0; ic < C0; ic++) {
            const float* seb = &se[ic][L];
            const float* sob = &so[ic][L];
            float4 ea = *(const float4*)(seb);
            float4 eb = *(const float4*)(seb + 4);
            float2 ec = *(const float2*)(seb + 8);
            float4 oa = *(const float4*)(sob);
            float4 ob = *(const float4*)(sob + 4);
            float2 ocv = *(const float2*)(sob + 8);
            float od = sob[10];
            float e[10] = {ea.x, ea.y, ea.z, ea.w, eb.x, eb.y, eb.z, eb.w, ec.x, ec.y};
            float o[11] = {oa.x, oa.y, oa.z, oa.w, ob.x, ob.y, ob.z, ob.w, ocv.x, ocv.y, od};
            #pragma unroll
            for (int i = 0; i < 4; i++) {
                const float* wp = w1 + (oc + i) * 56 + ic * 7;
                float w0 = wp[0], w1_ = wp[1], w2 = wp[2], w3 = wp[3];
                float w4 = wp[4], w5 = wp[5], w6 = wp[6];
                #pragma unroll
                for (int u = 0; u < 8; u++) {
                    float s = acc[i][u];
                    s += e[u] * w1_ + e[u + 1] * w3 + e[u + 2] * w5;
                    s += o[u] * w0 + o[u + 1] * w2 + o[u + 2] * w4 + o[u + 3] * w6;
                    acc[i][u] = s;
                }
            }
        }
        #pragma unroll
        for (int i = 0; i < 4; i++) {
            float* op = g_z1 + (b * C1 + oc + i) * T1_ + t0 + L;
            float4 s0 = {fmaxf(acc[i][0], 0.f), fmaxf(acc[i][1], 0.f),
                         fmaxf(acc[i][2], 0.f), fmaxf(acc[i][3], 0.f)};
            float4 s1 = {fmaxf(acc[i][4], 0.f), fmaxf(acc[i][5], 0.f),
                         fmaxf(acc[i][6], 0.f), fmaxf(acc[i][7], 0.f)};
            *(float4*)op = s0;
            *(float4*)(op + 4) = s1;
        }
    }
}

// ============================================================================
// conv2: z1 -> z2[16,128,8192], k=5 s=2 p=2, relu
// out[t] = xe[t-1]w0 + xo[t-1]w1 + xe[t]w2 + xo[t]w3 + xe[t+1]w4
// tile 128 outputs, grid.z=2 splits ocs; thread TT=4, 2 quads of TO=4, 2 ic chunks
// ============================================================================
__global__ __launch_bounds__(256) void k_conv2(const float* __restrict__ w2,
                                               const float* __restrict__ b2) {
    __shared__ float se[32][132];   // se[ic][j] = X[2t0-2+2j], j<130
    __shared__ float so[32][132];   // so[ic][j] = X[2t0-1+2j], j<129
    int b = blockIdx.y, t0 = blockIdx.x * 128, zz = blockIdx.z;
    const float* xin = g_z1 + b * C1 * T1_;
    int lane = threadIdx.x & 31, w = threadIdx.x >> 5;
    int L = lane * 4;
    float acc[2][4][4];
    #pragma unroll
    for (int q = 0; q < 2; q++) {
        int oc = zz * 64 + w * 8 + q * 4;
        #pragma unroll
        for (int i = 0; i < 4; i++) {
            float bv = b2[oc + i];
            #pragma unroll
            for (int u = 0; u < 4; u++) acc[q][i][u] = bv;
        }
    }
    for (int ch = 0; ch < 2; ch++) {
        for (int idx = threadIdx.x; idx < 32 * 130; idx += 256) {
            int ic = idx / 130, j = idx - ic * 130;
            int icg = ch * 32 + ic;
            int f = 2 * t0 - 2 + 2 * j;
            float a  = (f >= 0 && f < T1_)         ? xin[icg * T1_ + f]     : 0.f;
            float bb = (f + 1 >= 0 && f + 1 < T1_) ? xin[icg * T1_ + f + 1] : 0.f;
            se[ic][j] = a;
            if (j < 129) so[ic][j] = bb;
        }
        __syncthreads();
        for (int ic = 0; ic < 32; ic++) {
            int icg = ch * 32 + ic;
            const float* seb = &se[ic][L];
            const float* sob = &so[ic][L];
            float4 ea = *(const float4*)(seb);
            float2 eb = *(const float2*)(seb + 4);
            float4 oa = *(const float4*)(sob);
            float ob = sob[4];
            float e[6] = {ea.x, ea.y, ea.z, ea.w, eb.x, eb.y};
            float o[5] = {oa.x, oa.y, oa.z, oa.w, ob};
            #pragma unroll
            for (int q = 0; q < 2; q++) {
                int oc = zz * 64 + w * 8 + q * 4;
                #pragma unroll
                for (int i = 0; i < 4; i++) {
                    const float* wp = w2 + (oc + i) * 320 + icg * 5;
                    float w0 = wp[0], w1_ = wp[1], w2_ = wp[2], w3 = wp[3], w4 = wp[4];
                    #pragma unroll
                    for (int u = 0; u < 4; u++) {
                        float s = acc[q][i][u];
                        s += e[u] * w0 + o[u] * w1_ + e[u + 1] * w2_;
                        s += o[u + 1] * w3 + e[u + 2] * w4;
                        acc[q][i][u] = s;
                    }
                }
            }
        }
        __syncthreads();
    }
    #pragma unroll
    for (int q = 0; q < 2; q++) {
        int oc = zz * 64 + w * 8 + q * 4;
        #pragma unroll
        for (int i = 0; i < 4; i++) {
            float* op = g_z2 + (b * C2 + oc + i) * T2_ + t0 + L;
            float4 s0 = {fmaxf(acc[q][i][0], 0.f), fmaxf(acc[q][i][1], 0.f),
                         fmaxf(acc[q][i][2], 0.f), fmaxf(acc[q][i][3], 0.f)};
            *(float4*)op = s0;
        }
    }
}

// ============================================================================
// conv3: z2 -> z_e[16,64,4096], k=3 s=2 p=1 (no relu)
// out[t] = xo[t-1]w0 + xe[t]w1 + xo[t]w2
// tile 128 outputs, thread TT=4, 2 quads of TO=4, 4 ic chunks of 32
// ============================================================================
__global__ __launch_bounds__(256) void k_conv3(const float* __restrict__ w3,
                                               const float* __restrict__ b3) {
    __shared__ float se[32][132];   // se[ic][j] = X[2t0+2j], j<128
    __shared__ float so[32][132];   // so[ic][j] = X[2t0-1+2j], j<129
    int b = blockIdx.y, t0 = blockIdx.x * 128;
    const float* xin = g_z2 + b * C2 * T2_;
    int lane = threadIdx.x & 31, w = threadIdx.x >> 5;
    int L = lane * 4;
    float acc[2][4][4];
    #pragma unroll
    for (int q = 0; q < 2; q++) {
        int oc = w * 8 + q * 4;
        #pragma unroll
        for (int i = 0; i < 4; i++) {
            float bv = b3[oc + i];
            #pragma unroll
            for (int u = 0; u < 4; u++) acc[q][i][u] = bv;
        }
    }
    for (int ch = 0; ch < 4; ch++) {
        for (int idx = threadIdx.x; idx < 32 * 129; idx += 256) {
            int ic = idx / 129, j = idx - ic * 129;
            int icg = ch * 32 + ic;
            int f = 2 * t0 - 2 + 2 * j;
            float a  = (f >= 0 && f < T2_)         ? xin[icg * T2_ + f]     : 0.f;
            float bb = (f + 1 >= 0 && f + 1 < T2_) ? xin[icg * T2_ + f + 1] : 0.f;
            if (j >= 1) se[ic][j - 1] = a;
            so[ic][j] = bb;
        }
        __syncthreads();
        for (int ic = 0; ic < 32; ic++) {
            int icg = ch * 32 + ic;
            float4 ea = *(const float4*)&se[ic][L];
            float4 oa = *(const float4*)&so[ic][L];
            float ob = so[ic][L + 4];
            float e[4] = {ea.x, ea.y, ea.z, ea.w};
            float o[5] = {oa.x, oa.y, oa.z, oa.w, ob};
            #pragma unroll
            for (int q = 0; q < 2; q++) {
                int oc = w * 8 + q * 4;
                #pragma unroll
                for (int i = 0; i < 4; i++) {
                    const float* wp = w3 + (oc + i) * 384 + icg * 3;
                    float w0 = wp[0], w1_ = wp[1], w2_ = wp[2];
                    #pragma unroll
                    for (int u = 0; u < 4; u++)
                        acc[q][i][u] += o[u] * w0 + e[u] * w1_ + o[u + 1] * w2_;
                }
            }
        }
        __syncthreads();
    }
    #pragma unroll
    for (int q = 0; q < 2; q++) {
        int oc = w * 8 + q * 4;
        #pragma unroll
        for (int i = 0; i < 4; i++) {
            float* op = g_ze + (b * D_ + oc + i) * T3_ + t0 + L;
            float4 s0 = {acc[q][i][0], acc[q][i][1], acc[q][i][2], acc[q][i][3]};
            *(float4*)op = s0;
        }
    }
}

// ============================================================================
// quantize: z_e + codebook -> z_q, hist, vq SSE (FFMA2 dot products)
// ============================================================================
__global__ __launch_bounds__(256) void k_quant(const float* __restrict__ cb) {
    __shared__ __align__(16) float scb[128 * 64];
    __shared__ float snorm[128];
    __shared__ int   shist[NC];
    __shared__ float sred[8];
    int tid = threadIdx.x;
    int g = blockIdx.x * 256 + tid;
    int b = g >> 12, t = g & 4095;

    for (int i = tid; i < NC; i += 256) shist[i] = 0;

    float z[64];
    const float* zp = g_ze + b * D_ * T3_ + t;
    #pragma unroll
    for (int d = 0; d < 64; d++) z[d] = zp[d * T3_];
    float zz = 0.f;
    #pragma unroll
    for (int d = 0; d < 64; d++) zz += z[d] * z[d];
    ull z2[32];
    #pragma unroll
    for (int q = 0; q < 32; q++) z2[q] = pk(z[2 * q], z[2 * q + 1]);

    float best = 3.4e38f;
    int bi = 0;
    for (int ch = 0; ch < 4; ch++) {
        __syncthreads();
        for (int i = tid; i < 128 * 64; i += 256) scb[i] = cb[ch * 8192 + i];
        __syncthreads();
        for (int c = tid; c < 128; c += 256) {
            float n = 0.f;
            for (int d = 0; d < 64; d++) { float v = scb[c * 64 + d]; n += v * v; }
            snorm[c] = n;
        }
        __syncthreads();
        for (int c = 0; c < 128; c++) {
            const ulonglong2* cp = (const ulonglong2*)(scb + c * 64);
            ull d0 = 0ull, d1 = 0ull;
            #pragma unroll
            for (int q = 0; q < 16; q++) {
                ulonglong2 pv = cp[q];
                d0 = ffma2(z2[2 * q],     pv.x, d0);
                d1 = ffma2(z2[2 * q + 1], pv.y, d1);
            }
            float a0, a1, a2, a3;
            upk(d0, a0, a1); upk(d1, a2, a3);
            float dot = (a0 + a1) + (a2 + a3);
            float d2 = zz - 2.f * dot + snorm[c];
            if (d2 < best) { best = d2; bi = ch * 128 + c; }
        }
    }

    // exact SSE against chosen code + write z_q
    const float* cbest = cb + bi * 64;
    float* zqp = g_zq + b * D_ * T3_ + t;
    float sse = 0.f;
    #pragma unroll
    for (int d = 0; d < 64; d++) {
        float cv = __ldg(&cbest[d]);
        float df = z[d] - cv;
        sse += df * df;
        zqp[d * T3_] = cv;
    }
    atomicAdd(&shist[bi], 1);

    int lane = tid & 31, w = tid >> 5;
    #pragma unroll
    for (int off = 16; off; off >>= 1) sse += __shfl_down_sync(0xffffffffu, sse, off);
    if (lane == 0) sred[w] = sse;
    __syncthreads();
    if (tid < 8) {
        float v = sred[tid];
        #pragma unroll
        for (int off = 4; off; off >>= 1) v += __shfl_down_sync(0xffu, v, off);
        if (tid == 0) atomicAdd(&g_vq_sse, (double)v);
    }
    __syncthreads();
    for (int i = tid; i < NC; i += 256)
        if (shist[i]) atomicAdd(&g_hist[b * NC + i], shist[i]);
}

// ---------------- conditioning = hist @ codebook / T3 ----------------------
__global__ void k_cond(const float* __restrict__ cb, float* __restrict__ out) {
    int b = blockIdx.x, d = threadIdx.x;
    float sum = 0.f;
    for (int c = 0; c < NC; c++)
        sum += (float)g_hist[b * NC + c] * cb[c * 64 + d];
    out[b * 64 + d] = sum * (1.f / (float)T3_);
}

// ============================================================================
// decoder convT pattern: out[2m] = x[m-1]w3 + x[m]w1 ; out[2m+1] = x[m]w2 + x[m+1]w0
// packed: acc2(2m,2m+1) += {x[m-1],x[m]}*{w3,w2} + {x[m],x[m+1]}*{w1,w0}
// ============================================================================

// decT1: z_q[16,64,4096] -> r1[16,128,8192], relu. tile: 128 inputs -> 256 outputs
__global__ __launch_bounds__(256) void k_dec1(const float* __restrict__ dw1,
                                              const float* __restrict__ db1) {
    __shared__ float s[64][132];    // s[ic][j] = X[m0-1+j], j<130
    int b = blockIdx.y, m0 = blockIdx.x * 128;
    const float* xin = g_zq + b * D_ * T3_;
    for (int idx = threadIdx.x; idx < 64 * 130; idx += 256) {
        int ic = idx / 130, j = idx - ic * 130;
        int gg = m0 - 1 + j;
        s[ic][j] = (gg >= 0 && gg < T3_) ? xin[ic * T3_ + gg] : 0.f;
    }
    __syncthreads();
    int lane = threadIdx.x & 31, w = threadIdx.x >> 5;
    int M0 = lane * 4;
    for (int q = 0; q < 4; q++) {
        int oc = w * 16 + q * 4;
        ull acc[4][4];
        #pragma unroll
        for (int i = 0; i < 4; i++) {
            float bv = db1[oc + i];
            ull pb_ = pk(bv, bv);
            #pragma unroll
            for (int d = 0; d < 4; d++) acc[i][d] = pb_;
        }
        for (int ic = 0; ic < 64; ic++) {
            float4 v = *(const float4*)&s[ic][M0];
            float2 v2 = *(const float2*)&s[ic][M0 + 4];
            ull pm10 = pk(v.x, v.y), p01 = pk(v.y, v.z), p12 = pk(v.z, v.w);
            ull p23 = pk(v.w, v2.x), p34 = pk(v2.x, v2.y);
            #pragma unroll
            for (int i = 0; i < 4; i++) {
                float4 wv = *(const float4*)(dw1 + (ic * C2 + oc + i) * 4);
                ull w32 = pk(wv.w, wv.z), w10 = pk(wv.y, wv.x);
                acc[i][0] = ffma2(p01, w10, ffma2(pm10, w32, acc[i][0]));
                acc[i][1] = ffma2(p12, w10, ffma2(p01,  w32, acc[i][1]));
                acc[i][2] = ffma2(p23, w10, ffma2(p12,  w32, acc[i][2]));
                acc[i][3] = ffma2(p34, w10, ffma2(p23,  w32, acc[i][3]));
            }
        }
        #pragma unroll
        for (int i = 0; i < 4; i++) {
            float r0, r1, r2, r3, r4, r5, r6, r7;
            upk(acc[i][0], r0, r1); upk(acc[i][1], r2, r3);
            upk(acc[i][2], r4, r5); upk(acc[i][3], r6, r7);
            float* op = g_r1 + (b * C2 + oc + i) * T2_ + 2 * m0 + lane * 8;
            float4 s0 = {fmaxf(r0, 0.f), fmaxf(r1, 0.f), fmaxf(r2, 0.f), fmaxf(r3, 0.f)};
            float4 s1 = {fmaxf(r4, 0.f), fmaxf(r5, 0.f), fmaxf(r6, 0.f), fmaxf(r7, 0.f)};
            *(float4*)op = s0;
            *(float4*)(op + 4) = s1;
        }
    }
}

// decT2: r1[16,128,8192] -> r2[16,64,16384], relu. grid.z=2 splits ocs; 2 ic chunks
__global__ __launch_bounds__(256) void k_dec2(const float* __restrict__ dw2,
                                              const float* __restrict__ db2) {
    __shared__ float s[64][132];
    int b = blockIdx.y, m0 = blockIdx.x * 128, zz = blockIdx.z;
    const float* xin = g_r1 + b * C2 * T2_;
    int lane = threadIdx.x & 31, w = threadIdx.x >> 5;
    int M0 = lane * 4;
    int oc = zz * 32 + w * 4;
    ull acc[4][4];
    #pragma unroll
    for (int i = 0; i < 4; i++) {
        float bv = db2[oc + i];
        ull pb_ = pk(bv, bv);
        #pragma unroll
        for (int d = 0; d < 4; d++) acc[i][d] = pb_;
    }
    for (int ch = 0; ch < 2; ch++) {
        for (int idx = threadIdx.x; idx < 64 * 130; idx += 256) {
            int ic = idx / 130, j = idx - ic * 130;
            int icg = ch * 64 + ic;
            int gg = m0 - 1 + j;
            s[ic][j] = (gg >= 0 && gg < T2_) ? xin[icg * T2_ + gg] : 0.f;
        }
        __syncthreads();
        for (int ic = 0; ic < 64; ic++) {
            int icg = ch * 64 + ic;
            float4 v = *(const float4*)&s[ic][M0];
            float2 v2 = *(const float2*)&s[ic][M0 + 4];
            ull pm10 = pk(v.x, v.y), p01 = pk(v.y, v.z), p12 = pk(v.z, v.w);
            ull p23 = pk(v.w, v2.x), p34 = pk(v2.x, v2.y);
            #pragma unroll
            for (int i = 0; i < 4; i++) {
                float4 wv = *(const float4*)(dw2 + (icg * C1 + oc + i) * 4);
                ull w32 = pk(wv.w, wv.z), w10 = pk(wv.y, wv.x);
                acc[i][0] = ffma2(p01, w10, ffma2(pm10, w32, acc[i][0]));
                acc[i][1] = ffma2(p12, w10, ffma2(p01,  w32, acc[i][1]));
                acc[i][2] = ffma2(p23, w10, ffma2(p12,  w32, acc[i][2]));
                acc[i][3] = ffma2(p34, w10, ffma2(p23,  w32, acc[i][3]));
            }
        }
        __syncthreads();
    }
    #pragma unroll
    for (int i = 0; i < 4; i++) {
        float r0, r1, r2, r3, r4, r5, r6, r7;
        upk(acc[i][0], r0, r1); upk(acc[i][1], r2, r3);
        upk(acc[i][2], r4, r5); upk(acc[i][3], r6, r7);
        float* op = g_r2 + (b * C1 + oc + i) * T1_ + 2 * m0 + lane * 8;
        float4 s0 = {fmaxf(r0, 0.f), fmaxf(r1, 0.f), fmaxf(r2, 0.f), fmaxf(r3, 0.f)};
        float4 s1 = {fmaxf(r4, 0.f), fmaxf(r5, 0.f), fmaxf(r6, 0.f), fmaxf(r7, 0.f)};
        *(float4*)op = s0;
        *(float4*)(op + 4) = s1;
    }
}

// decT3 fused with recon-MSE: r2[16,64,16384] -> (x_recon - x)^2 sum (no relu)
__global__ __launch_bounds__(256) void k_dec3(const float* __restrict__ dw3,
                                              const float* __restrict__ db3,
                                              const float* __restrict__ x) {
    __shared__ float s[64][132];
    __shared__ float sred[8];
    int b = blockIdx.y, m0 = blockIdx.x * 128;
    const float* xin = g_r2 + b * C1 * T1_;
    for (int idx = threadIdx.x; idx < 64 * 130; idx += 256) {
        int ic = idx / 130, j = idx - ic * 130;
        int gg = m0 - 1 + j;
        s[ic][j] = (gg >= 0 && gg < T1_) ? xin[ic * T1_ + gg] : 0.f;
    }
    __syncthreads();
    int lane = threadIdx.x & 31, w = threadIdx.x >> 5;
    int M0 = lane * 4;
    int oc = w;                      // 8 warps <-> 8 output channels
    ull acc[4];
    {
        float bv = db3[oc];
        ull pb_ = pk(bv, bv);
        #pragma unroll
        for (int d = 0; d < 4; d++) acc[d] = pb_;
    }
    for (int ic = 0; ic < 64; ic++) {
        float4 v = *(const float4*)&s[ic][M0];
        float2 v2 = *(const float2*)&s[ic][M0 + 4];
        ull pm10 = pk(v.x, v.y), p01 = pk(v.y, v.z), p12 = pk(v.z, v.w);
        ull p23 = pk(v.w, v2.x), p34 = pk(v2.x, v2.y);
        float4 wv = *(const float4*)(dw3 + (ic * C0 + oc) * 4);
        ull w32 = pk(wv.w, wv.z), w10 = pk(wv.y, wv.x);
        acc[0] = ffma2(p01, w10, ffma2(pm10, w32, acc[0]));
        acc[1] = ffma2(p12, w10, ffma2(p01,  w32, acc[1]));
        acc[2] = ffma2(p23, w10, ffma2(p12,  w32, acc[2]));
        acc[3] = ffma2(p34, w10, ffma2(p23,  w32, acc[3]));
    }
    float r0, r1, r2, r3, r4, r5, r6, r7;
    upk(acc[0], r0, r1); upk(acc[1], r2, r3);
    upk(acc[2], r4, r5); upk(acc[3], r6, r7);
    const float* xr = x + (b * C0 + oc) * T0_ + 2 * m0 + lane * 8;
    float4 xa = *(const float4*)xr;
    float4 xb = *(const float4*)(xr + 4);
    float d0 = r0 - xa.x, d1 = r1 - xa.y, d2 = r2 - xa.z, d3 = r3 - xa.w;
    float d4 = r4 - xb.x, d5 = r5 - xb.y, d6 = r6 - xb.z, d7 = r7 - xb.w;
    float ssq = d0 * d0 + d1 * d1 + d2 * d2 + d3 * d3
              + d4 * d4 + d5 * d5 + d6 * d6 + d7 * d7;
    #pragma unroll
    for (int off = 16; off; off >>= 1) ssq += __shfl_down_sync(0xffffffffu, ssq, off);
    if (lane == 0) sred[w] = ssq;
    __syncthreads();
    if (threadIdx.x < 8) {
        float v = sred[threadIdx.x];
        #pragma unroll
        for (int off = 4; off; off >>= 1) v += __shfl_down_sync(0xffu, v, off);
        if (threadIdx.x == 0) atomicAdd(&g_rec_sse, (double)v);
    }
}

// ---------------- finalize scalars -----------------------------------------
__global__ void k_fin(float* __restrict__ out, int out_size) {
    if (out_size >= 1027) {
        float vq = (float)(g_vq_sse / (double)(B_ * D_ * T3_));
        out[1024] = vq;
        out[1025] = vq;
        out[1026] = (float)(g_rec_sse / (double)(B_ * C0 * T0_));
    }
}

// ---------------- launch ----------------------------------------------------
extern "C" void kernel_launch(void* const* d_in, const int* in_sizes, int n_in,
                              void* d_out, int out_size) {
    const float* x   = (const float*)d_in[0];
    const float* w1  = (const float*)d_in[1];
    const float* b1  = (const float*)d_in[2];
    const float* w2  = (const float*)d_in[3];
    const float* b2  = (const float*)d_in[4];
    const float* w3  = (const float*)d_in[5];
    const float* b3  = (const float*)d_in[6];
    const float* cb  = (const float*)d_in[7];
    const float* dw1 = (const float*)d_in[8];
    const float* db1 = (const float*)d_in[9];
    const float* dw2 = (const float*)d_in[10];
    const float* db2 = (const float*)d_in[11];
    const float* dw3 = (const float*)d_in[12];
    const float* db3 = (const float*)d_in[13];
    float* out = (float*)d_out;

    k_init<<<32, 256>>>();
    k_conv1<<<dim3(T1_ / 256, B_), 256>>>(x, w1, b1);
    k_conv2<<<dim3(T2_ / 128, B_, 2), 256>>>(w2, b2);
    k_conv3<<<dim3(T3_ / 128, B_), 256>>>(w3, b3);
    k_quant<<<(B_ * T3_) / 256, 256>>>(cb);
    k_cond<<<B_, 64>>>(cb, out);
    k_dec1<<<dim3(T3_ / 128, B_), 256>>>(dw1, db1);
    k_dec2<<<dim3(T2_ / 128, B_, 2), 256>>>(dw2, db2);
    k_dec3<<<dim3(T1_ / 128, B_), 256>>>(dw3, db3, x);
    k_fin<<<1, 1>>>(out, out_size);
}